// round 6
// baseline (speedup 1.0000x reference)
#include <cuda_runtime.h>
#include <cuda_bf16.h>

#define MAXN 50000
#define MAXE 1000000
#define SCAN_B 256

typedef unsigned long long ull;

// Scratch (__device__ globals; no allocation allowed)
__device__ float g_we[MAXE];        // per-edge MLP output
__device__ ull   g_csr[MAXE];       // dst-sorted entries: (we_bits<<32)|src
__device__ int   g_degi[MAXN];      // in-degree (int)
__device__ int   g_part[MAXN];      // scan partials
__device__ int   g_bsum[(MAXN + SCAN_B - 1) / SCAN_B];
__device__ int   g_boff[(MAXN + SCAN_B - 1) / SCAN_B];
__device__ int   g_fill[MAXN];      // placement cursors
__device__ float4 g_meta[MAXN];     // {start, deg, inv, -}
__device__ float g_hA[MAXN];
__device__ float g_hB[MAXN];

// ---- packed f32x2 helpers ---------------------------------------------------
__device__ __forceinline__ ull pack2(float lo, float hi) {
    ull r; asm("mov.b64 %0, {%1,%2};" : "=l"(r) : "f"(lo), "f"(hi)); return r;
}
__device__ __forceinline__ void unpack2(ull v, float& lo, float& hi) {
    asm("mov.b64 {%0,%1}, %2;" : "=f"(lo), "=f"(hi) : "l"(v));
}
__device__ __forceinline__ ull fma2(ull a, ull b, ull c) {
    ull d; asm("fma.rn.f32x2 %0, %1, %2, %3;" : "=l"(d) : "l"(a), "l"(b), "l"(c)); return d;
}

// ---- PDL: trigger AFTER all writes; wait BEFORE first read of pred's writes --
__device__ __forceinline__ void pdl_trigger() {
    asm volatile("griddepcontrol.launch_dependents;");
}
__device__ __forceinline__ void pdl_wait() {
    asm volatile("griddepcontrol.wait;" ::: "memory");
}

// ---------------------------------------------------------------------------
__global__ void k_init(const float* __restrict__ x, int n) {
    int i = blockIdx.x * blockDim.x + threadIdx.x;
    if (i < n) {
        g_degi[i] = 0;
        g_hA[i]   = x[5 * i + 2];
    }
}

// ---------------------------------------------------------------------------
// Edge MLP: we = relu(ea@w1+b1)@w2+b2 (packed f32x2, 4 edges/group) + int deg.
__global__ void __launch_bounds__(256, 6)
k_edge_mlp(const float* __restrict__ ea,
           const int*   __restrict__ dst,
           const float* __restrict__ w1,
           const float* __restrict__ b1,
           const float* __restrict__ w2,
           const float* __restrict__ b2,
           int E_) {
    __shared__ ull s_w1[192];
    __shared__ ull s_b1[64];
    __shared__ ull s_w2[64];
    int t = threadIdx.x;
    if (t < 192) { float w = w1[t]; s_w1[t] = pack2(w, w); }
    if (t < 64)  { float b = b1[t]; s_b1[t] = pack2(b, b);
                   float w = w2[t]; s_w2[t] = pack2(w, w); }
    __syncthreads();

    const int nth = gridDim.x * blockDim.x;
    const int tid = blockIdx.x * blockDim.x + t;
    const float b2v = b2[0];
    const int ngroups = (E_ + 3) >> 2;

    for (int g = tid; g < ngroups; g += nth) {
        int e0 = g * 4;
        if (e0 + 3 < E_) {
            const float4* p = (const float4*)(ea + 3 * e0);
            float4 v0 = p[0], v1 = p[1], v2 = p[2];
            ull pa0 = pack2(v0.x, v0.w), pa1 = pack2(v0.y, v1.x), pa2 = pack2(v0.z, v1.y);
            ull pb0 = pack2(v1.z, v2.y), pb1 = pack2(v1.w, v2.z), pb2 = pack2(v2.x, v2.w);
            ull accA = pack2(b2v, b2v), accB = accA;
#pragma unroll 8
            for (int j = 0; j < 64; j++) {
                ull c0 = s_w1[j], c1 = s_w1[64 + j], c2 = s_w1[128 + j];
                ull bb = s_b1[j], ww = s_w2[j];
                ull hA = fma2(pa2, c2, bb); hA = fma2(pa1, c1, hA); hA = fma2(pa0, c0, hA);
                ull hB = fma2(pb2, c2, bb); hB = fma2(pb1, c1, hB); hB = fma2(pb0, c0, hB);
                float l, h;
                unpack2(hA, l, h); l = fmaxf(l, 0.f); h = fmaxf(h, 0.f);
                accA = fma2(pack2(l, h), ww, accA);
                unpack2(hB, l, h); l = fmaxf(l, 0.f); h = fmaxf(h, 0.f);
                accB = fma2(pack2(l, h), ww, accB);
            }
            float r0, r1, r2, r3;
            unpack2(accA, r0, r1); unpack2(accB, r2, r3);
            *(float4*)(g_we + e0) = make_float4(r0, r1, r2, r3);
            int4 d = *(const int4*)(dst + e0);
            atomicAdd(&g_degi[d.x], 1);
            atomicAdd(&g_degi[d.y], 1);
            atomicAdd(&g_degi[d.z], 1);
            atomicAdd(&g_degi[d.w], 1);
        } else {
            for (int e = e0; e < E_; e++) {
                float a0 = ea[3 * e], a1 = ea[3 * e + 1], a2 = ea[3 * e + 2];
                float acc = b2v;
                for (int j = 0; j < 64; j++) {
                    float wl, wh, xl, xh, yl, yh, bl, bh, zl, zh;
                    unpack2(s_w1[j], wl, wh); unpack2(s_w1[64 + j], xl, xh);
                    unpack2(s_w1[128 + j], yl, yh); unpack2(s_b1[j], bl, bh);
                    unpack2(s_w2[j], zl, zh);
                    float hj = fmaf(a0, wl, fmaf(a1, xl, fmaf(a2, yl, bl)));
                    acc = fmaf(fmaxf(hj, 0.f), zl, acc);
                }
                g_we[e] = acc;
                atomicAdd(&g_degi[dst[e]], 1);
            }
        }
    }
}

// ---------------------------------------------------------------------------
// Hierarchical exclusive scan of g_degi -> row starts.
__global__ void k_scan1(int n) {
    __shared__ int sh[SCAN_B];
    int tid = threadIdx.x;
    int i = blockIdx.x * SCAN_B + tid;
    int v = (i < n) ? g_degi[i] : 0;
    sh[tid] = v;
    __syncthreads();
    for (int o = 1; o < SCAN_B; o <<= 1) {
        int tv = (tid >= o) ? sh[tid - o] : 0;
        __syncthreads();
        sh[tid] += tv;
        __syncthreads();
    }
    if (i < n) g_part[i] = sh[tid] - v;             // exclusive within block
    if (tid == SCAN_B - 1) g_bsum[blockIdx.x] = sh[tid];
}

__global__ void k_scan2(int nb) {
    __shared__ int sh[SCAN_B];
    int tid = threadIdx.x;
    int v = (tid < nb) ? g_bsum[tid] : 0;
    sh[tid] = v;
    __syncthreads();
    for (int o = 1; o < SCAN_B; o <<= 1) {
        int tv = (tid >= o) ? sh[tid - o] : 0;
        __syncthreads();
        sh[tid] += tv;
        __syncthreads();
    }
    if (tid < nb) g_boff[tid] = sh[tid] - v;        // exclusive block offsets
}

__global__ void k_scan3(int n) {
    int i = blockIdx.x * blockDim.x + threadIdx.x;
    if (i >= n) return;
    int start = g_part[i] + g_boff[i / SCAN_B];
    int deg   = g_degi[i];
    float inv = (deg > 0) ? (1.0f / (float)deg) : 0.0f;
    g_fill[i] = start;
    float4 m;
    m.x = __int_as_float(start);
    m.y = __int_as_float(deg);
    m.z = inv;
    m.w = 0.0f;
    g_meta[i] = m;
}

// ---------------------------------------------------------------------------
// Placement: csr[pos(dst)] = (we_bits<<32)|src   (counting-sort by dst)
__global__ void __launch_bounds__(256)
k_place(const int* __restrict__ src,
        const int* __restrict__ dst, int E_) {
    int i = blockIdx.x * blockDim.x + threadIdx.x;
    int e = i * 4;
    if (e + 3 < E_) {
        int4   s = *(const int4*)(src + e);
        int4   d = *(const int4*)(dst + e);
        float4 w = *(const float4*)(g_we + e);
        int p0 = atomicAdd(&g_fill[d.x], 1);
        int p1 = atomicAdd(&g_fill[d.y], 1);
        int p2 = atomicAdd(&g_fill[d.z], 1);
        int p3 = atomicAdd(&g_fill[d.w], 1);
        g_csr[p0] = ((ull)__float_as_uint(w.x) << 32) | (unsigned)s.x;
        g_csr[p1] = ((ull)__float_as_uint(w.y) << 32) | (unsigned)s.y;
        g_csr[p2] = ((ull)__float_as_uint(w.z) << 32) | (unsigned)s.z;
        g_csr[p3] = ((ull)__float_as_uint(w.w) << 32) | (unsigned)s.w;
    } else {
        for (; e < E_; e++) {
            int p = atomicAdd(&g_fill[dst[e]], 1);
            g_csr[p] = ((ull)__float_as_uint(g_we[e]) << 32) | (unsigned)src[e];
        }
    }
}

// ---------------------------------------------------------------------------
// Fused gather + update, warp per node. No atomics, no agg.
// Pre-wait: meta/csr (immutable), root/bias. Post-wait: h_in reads.
__global__ void __launch_bounds__(256)
k_gather(const float* __restrict__ root,
         const float* __restrict__ bias,
         float* __restrict__ out,
         int n, int flag, int write_out) {
    int node = (blockIdx.x * blockDim.x + threadIdx.x) >> 5;
    int lane = threadIdx.x & 31;
    const float* __restrict__ h_in  = flag ? g_hB : g_hA;
    float* __restrict__       h_out = flag ? g_hA : g_hB;

    if (node < n) {
        float4 m  = g_meta[node];           // uniform 16B load
        int start = __float_as_int(m.x);
        int deg   = __float_as_int(m.y);
        float inv = m.z;
        float r   = root[0];
        float b   = bias[0];
        // pre-wait: stream first batch of csr entries (immutable)
        ull e0 = 0;
        if (lane < deg) e0 = g_csr[start + lane];

        pdl_wait();

        float sum = 0.0f;
        if (lane < deg) {
            unsigned s = (unsigned)(e0 & 0xFFFFFFFFull);
            float    w = __uint_as_float((unsigned)(e0 >> 32));
            sum = h_in[s] * w;
        }
        for (int j = lane + 32; j < deg; j += 32) {
            ull e = g_csr[start + j];
            unsigned s = (unsigned)(e & 0xFFFFFFFFull);
            float    w = __uint_as_float((unsigned)(e >> 32));
            sum = fmaf(h_in[s], w, sum);
        }
#pragma unroll
        for (int o = 16; o; o >>= 1)
            sum += __shfl_down_sync(0xFFFFFFFFu, sum, o);

        if (lane == 0) {
            float hv = h_in[node];
            float v = fmaxf(fmaf(sum, inv, fmaf(hv, r, b)), 0.0f);
            h_out[node] = v;
            if (write_out) out[node] = v;
        }
    } else {
        pdl_wait();
    }
    pdl_trigger();
}

// ---------------------------------------------------------------------------
extern "C" void kernel_launch(void* const* d_in, const int* in_sizes, int n_in,
                              void* d_out, int out_size) {
    const float* x    = (const float*)d_in[0];
    const int*   ei   = (const int*)  d_in[1];
    const float* ea   = (const float*)d_in[2];
    const float* w1   = (const float*)d_in[3];
    const float* b1   = (const float*)d_in[4];
    const float* w2   = (const float*)d_in[5];
    const float* b2   = (const float*)d_in[6];
    const float* root = (const float*)d_in[7];
    const float* bias = (const float*)d_in[8];
    float* out = (float*)d_out;

    const int E_ = in_sizes[1] / 2;
    const int N_ = in_sizes[0] / 5;
    const int* src = ei;
    const int* dst = ei + E_;

    int sms = 148;
    cudaDeviceGetAttribute(&sms, cudaDevAttrMultiProcessorCount, 0);

    cudaLaunchAttribute pdlAttr[1];
    pdlAttr[0].id = cudaLaunchAttributeProgrammaticStreamSerialization;
    pdlAttr[0].val.programmaticStreamSerializationAllowed = 1;

    const int nb = (N_ + SCAN_B - 1) / SCAN_B;
    const int ngroups = (E_ + 3) / 4;

    // Preamble: normal stream-serialized launches (correctness first).
    k_init<<<(N_ + 255) / 256, 256>>>(x, N_);
    k_edge_mlp<<<sms * 6, 256>>>(ea, dst, w1, b1, w2, b2, E_);
    k_scan1<<<nb, SCAN_B>>>(N_);
    k_scan2<<<1, SCAN_B>>>(nb);
    k_scan3<<<nb, SCAN_B>>>(N_);
    k_place<<<(ngroups + 255) / 256, 256>>>(src, dst, E_);

    // 4 fused gather+update iterations; PDL chains them (gather t+1 streams
    // immutable csr/meta during gather t's drain).
    const int gblocks = (N_ * 32 + 255) / 256;   // warp per node
    for (int t = 0; t < 4; t++) {
        int flag = t & 1;
        int wo   = (t == 3) ? 1 : 0;
        if (t == 0) {
            k_gather<<<gblocks, 256>>>(root, bias, out, N_, flag, wo);
        } else {
            cudaLaunchConfig_t cfg = {};
            cfg.gridDim  = dim3(gblocks, 1, 1);
            cfg.blockDim = dim3(256, 1, 1);
            cfg.stream   = 0;
            cfg.attrs    = pdlAttr;
            cfg.numAttrs = 1;
            cudaLaunchKernelEx(&cfg, k_gather, root, bias, out, N_, flag, wo);
        }
    }
}